// round 4
// baseline (speedup 1.0000x reference)
#include <cuda_runtime.h>
#include <math.h>

#define N_NODES 5000
#define E_EDGES 160000
#define F_HID   16

// ---- scratch (device globals: no allocation allowed) ----
__device__ float g_inv[N_NODES];            // deg -> rsqrt(deg)
__device__ float g_h1 [N_NODES * F_HID];    // x @ W1
__device__ float g_a1 [N_NODES * F_HID];    // A_hat @ h1
__device__ float g_hr [N_NODES * F_HID];    // relu(a1 + b1)
__device__ float g_p2 [N_NODES * F_HID];    // A_hat @ hr

// ---------------- degree / normalization ----------------
__global__ void k_deg_init() {
    int i = blockIdx.x * blockDim.x + threadIdx.x;
    if (i < N_NODES) g_inv[i] = 1.0f;   // self loop counts 1
}

__global__ void k_deg_edges(const int* __restrict__ dst) {
    int e = blockIdx.x * blockDim.x + threadIdx.x;
    if (e < E_EDGES) atomicAdd(&g_inv[dst[e]], 1.0f);
}

__global__ void k_rsqrt() {
    int i = blockIdx.x * blockDim.x + threadIdx.x;
    if (i < N_NODES) g_inv[i] = rsqrtf(g_inv[i]);
}

// ---------------- GEMM1: g_h1 = x[N,N] @ W1[N,16] ----------------
// Block = 256 threads (8 warps), 32 rows/block (4 rows/warp).
// W1 staged to smem transposed [j][kk] in chunks of 500 k's (conflict-free LDS).
#define G1_CH 500
__global__ void __launch_bounds__(256) k_gemm1(const float* __restrict__ x,
                                               const float* __restrict__ W1) {
    __shared__ float sW[F_HID * G1_CH];
    const int warp = threadIdx.x >> 5, lane = threadIdx.x & 31;
    const int row0 = blockIdx.x * 32 + warp * 4;

    float acc[4][16];
#pragma unroll
    for (int r = 0; r < 4; ++r)
#pragma unroll
        for (int j = 0; j < 16; ++j) acc[r][j] = 0.0f;

    for (int c = 0; c < N_NODES / G1_CH; ++c) {
        const int k0 = c * G1_CH;
        __syncthreads();
        for (int idx = threadIdx.x; idx < F_HID * G1_CH; idx += 256) {
            int kk = idx >> 4, j = idx & 15;
            sW[j * G1_CH + kk] = W1[(k0 + kk) * F_HID + j];
        }
        __syncthreads();

        for (int kk = lane; kk < G1_CH; kk += 32) {
            float xv[4];
#pragma unroll
            for (int r = 0; r < 4; ++r) {
                int row = row0 + r;
                xv[r] = (row < N_NODES) ? x[row * N_NODES + k0 + kk] : 0.0f;
            }
#pragma unroll
            for (int j = 0; j < 16; ++j) {
                float w = sW[j * G1_CH + kk];
#pragma unroll
                for (int r = 0; r < 4; ++r)
                    acc[r][j] = fmaf(xv[r], w, acc[r][j]);
            }
        }
    }

    // warp tree-reduce all 64 accumulators
#pragma unroll
    for (int r = 0; r < 4; ++r)
#pragma unroll
        for (int j = 0; j < 16; ++j)
#pragma unroll
            for (int o = 16; o; o >>= 1)
                acc[r][j] += __shfl_xor_sync(0xffffffffu, acc[r][j], o);

    if (lane == 0) {
#pragma unroll
        for (int r = 0; r < 4; ++r) {
            int row = row0 + r;
            if (row < N_NODES) {
#pragma unroll
                for (int j = 0; j < 16; ++j)
                    g_h1[row * F_HID + j] = acc[r][j];
            }
        }
    }
}

// ---------------- 16-wide propagation ----------------
__global__ void k_self1() {
    int t = blockIdx.x * blockDim.x + threadIdx.x;
    if (t >= N_NODES * F_HID) return;
    int i = t >> 4;
    float iv = g_inv[i];
    g_a1[t] = iv * iv * g_h1[t];
}

template <int L>
__global__ void k_edge_agg(const int* __restrict__ src, const int* __restrict__ dst) {
    int t = blockIdx.x * blockDim.x + threadIdx.x;
    if (t >= E_EDGES * F_HID) return;
    int e = t >> 4, j = t & 15;
    int s = src[e], d = dst[e];
    const float* feat  = (L == 1) ? g_h1 : g_hr;
    float*       accum = (L == 1) ? g_a1 : g_p2;
    float v = feat[s * F_HID + j] * g_inv[s] * g_inv[d];
    atomicAdd(&accum[d * F_HID + j], v);
}

__global__ void k_relu_self2(const float* __restrict__ b1) {
    int t = blockIdx.x * blockDim.x + threadIdx.x;
    if (t >= N_NODES * F_HID) return;
    int i = t >> 4, j = t & 15;
    float h = g_a1[t] + b1[j];
    h = fmaxf(h, 0.0f);
    g_hr[t] = h;
    float iv = g_inv[i];
    g_p2[t] = iv * iv * h;
}

// ---------------- GEMM2 + bias + log_softmax, fused ----------------
// Block = 256 threads, 8 full rows per block. z tile (8 x 5000 f32 = 160 KB)
// lives entirely in smem; p2 tile is register-resident per thread so the
// GEMM inner loop is pure LDG(W2, L2-hit) + FFMA. Then one warp per row does
// max / sum-exp / subtract and streams the final row to gmem.
__global__ void __launch_bounds__(256) k_gemm2(const float* __restrict__ W2,
                                               const float* __restrict__ b2,
                                               float* __restrict__ out) {
    extern __shared__ float sZ[];  // [8][N_NODES]
    const int row0 = blockIdx.x * 8;

    float p[8][16];
#pragma unroll
    for (int r = 0; r < 8; ++r)
#pragma unroll
        for (int k = 0; k < 16; ++k)
            p[r][k] = g_p2[(row0 + r) * F_HID + k];

    for (int c = threadIdx.x; c < N_NODES; c += 256) {
        float bv = b2[c];
        float acc[8];
#pragma unroll
        for (int r = 0; r < 8; ++r) acc[r] = bv;
#pragma unroll
        for (int k = 0; k < 16; ++k) {
            float w = W2[k * N_NODES + c];
#pragma unroll
            for (int r = 0; r < 8; ++r)
                acc[r] = fmaf(p[r][k], w, acc[r]);
        }
#pragma unroll
        for (int r = 0; r < 8; ++r) sZ[r * N_NODES + c] = acc[r];
    }
    __syncthreads();

    const int warp = threadIdx.x >> 5, lane = threadIdx.x & 31;
    const float* z = sZ + warp * N_NODES;

    float m = -INFINITY;
    for (int c = lane; c < N_NODES; c += 32) m = fmaxf(m, z[c]);
#pragma unroll
    for (int o = 16; o; o >>= 1) m = fmaxf(m, __shfl_xor_sync(0xffffffffu, m, o));

    float s = 0.0f;
    for (int c = lane; c < N_NODES; c += 32) s += __expf(z[c] - m);
#pragma unroll
    for (int o = 16; o; o >>= 1) s += __shfl_xor_sync(0xffffffffu, s, o);

    float lse = m + logf(s);
    float* orow = out + (size_t)(row0 + warp) * N_NODES;
    for (int c = lane; c < N_NODES; c += 32) orow[c] = z[c] - lse;
}

// ---------------- launch ----------------
extern "C" void kernel_launch(void* const* d_in, const int* in_sizes, int n_in,
                              void* d_out, int out_size) {
    const float* x   = (const float*)d_in[0];
    const int*   src = (const int*)  d_in[1];
    const int*   dst = (const int*)  d_in[2];
    const float* W1  = (const float*)d_in[3];
    const float* b1  = (const float*)d_in[4];
    const float* W2  = (const float*)d_in[5];
    const float* b2  = (const float*)d_in[6];
    float* out = (float*)d_out;

    const int smem2 = 8 * N_NODES * (int)sizeof(float);  // 160 KB
    cudaFuncSetAttribute(k_gemm2, cudaFuncAttributeMaxDynamicSharedMemorySize, smem2);

    k_deg_init <<<(N_NODES + 255) / 256, 256>>>();
    k_deg_edges<<<(E_EDGES + 255) / 256, 256>>>(dst);
    k_rsqrt    <<<(N_NODES + 255) / 256, 256>>>();

    k_gemm1<<<(N_NODES + 31) / 32, 256>>>(x, W1);

    k_self1<<<(N_NODES * F_HID + 255) / 256, 256>>>();
    k_edge_agg<1><<<(E_EDGES * F_HID + 255) / 256, 256>>>(src, dst);

    k_relu_self2<<<(N_NODES * F_HID + 255) / 256, 256>>>(b1);
    k_edge_agg<2><<<(E_EDGES * F_HID + 255) / 256, 256>>>(src, dst);

    k_gemm2<<<N_NODES / 8, 256, smem2>>>(W2, b2, out);
}

// round 5
// speedup vs baseline: 1.7133x; 1.7133x over previous
#include <cuda_runtime.h>
#include <math.h>

#define N_NODES 5000
#define E_EDGES 160000
#define F_HID   16

typedef unsigned long long ull;

// ---- scratch (device globals: no allocation allowed) ----
__device__ float g_inv[N_NODES];            // deg -> rsqrt(deg)
__device__ float g_h1 [N_NODES * F_HID];    // x @ W1  (atomic-accumulated)
__device__ float g_a1 [N_NODES * F_HID];    // A_hat @ h1
__device__ float g_hr [N_NODES * F_HID];    // relu(a1 + b1)
__device__ float g_p2 [N_NODES * F_HID];    // A_hat @ hr

// ---------------- f32x2 helpers ----------------
__device__ __forceinline__ ull ffma2(ull a, ull b, ull c) {
    ull d;
    asm("fma.rn.f32x2 %0, %1, %2, %3;" : "=l"(d) : "l"(a), "l"(b), "l"(c));
    return d;
}
__device__ __forceinline__ ull fpack(float lo, float hi) {
    ull r;
    asm("mov.b64 %0, {%1, %2};" : "=l"(r) : "f"(lo), "f"(hi));
    return r;
}
__device__ __forceinline__ float2 funpack(ull v) {
    float2 r;
    asm("mov.b64 {%0, %1}, %2;" : "=f"(r.x), "=f"(r.y) : "l"(v));
    return r;
}

// ---------------- init: zero g_h1, g_inv = 1 ----------------
__global__ void k_init() {
    int i = blockIdx.x * blockDim.x + threadIdx.x;
    if (i < N_NODES * F_HID) g_h1[i] = 0.0f;
    if (i < N_NODES) g_inv[i] = 1.0f;   // self loop counts 1
}

__global__ void k_deg_edges(const int* __restrict__ dst) {
    int e = blockIdx.x * blockDim.x + threadIdx.x;
    if (e < E_EDGES) atomicAdd(&g_inv[dst[e]], 1.0f);
}

__global__ void k_rsqrt() {
    int i = blockIdx.x * blockDim.x + threadIdx.x;
    if (i < N_NODES) g_inv[i] = rsqrtf(g_inv[i]);
}

// ---------------- GEMM1: g_h1 += x[N,N] @ W1[N,16]  (k-split) ----------------
// Block = 128 threads, 256 rows/block (2 rows/thread), K chunk = 64,
// K range per block = 320 (5 chunks), 16 k-splits. Grid = (20, 16) = 320 blocks.
// x tile staged to smem (padded stride 68 -> conflict-free LDS.128),
// W1 chunk broadcast from smem, packed fma.rn.f32x2 accumulation.
#define G1_ROWS 256
#define G1_KC   64
#define G1_KCP  68
#define G1_KR   320
#define G1_KS   16

__global__ void __launch_bounds__(128, 2) k_gemm1(const float* __restrict__ x,
                                                  const float* __restrict__ W1) {
    __shared__ float sX[G1_ROWS * G1_KCP];   // 69632 B
    __shared__ float sW[F_HID * G1_KC];      //  4096 B
    const int tid   = threadIdx.x;
    const int row0  = blockIdx.x * G1_ROWS;
    const int kbase = blockIdx.y * G1_KR;

    ull acc[2][F_HID];
#pragma unroll
    for (int r = 0; r < 2; ++r)
#pragma unroll
        for (int j = 0; j < F_HID; ++j) acc[r][j] = 0ull;   // (+0.0f, +0.0f)

    for (int ch = 0; ch < G1_KR / G1_KC; ++ch) {
        const int k0 = kbase + ch * G1_KC;
        __syncthreads();
        // stage W1 chunk transposed: sW[j][kk], zero-padded past N
        for (int idx = tid; idx < F_HID * G1_KC; idx += 128) {
            int kk = idx >> 4, j = idx & 15;
            int gk = k0 + kk;
            sW[j * G1_KC + kk] = (gk < N_NODES) ? W1[gk * F_HID + j] : 0.0f;
        }
        // stage x tile: 256 rows x 64 cols, float4 coalesced
        for (int idx = tid; idx < G1_ROWS * (G1_KC / 4); idx += 128) {
            int r = idx >> 4, c4 = idx & 15;
            int row = row0 + r; if (row >= N_NODES) row = N_NODES - 1;  // clamp; write-guarded
            int gk = k0 + c4 * 4;
            float4 v = (gk < N_NODES)
                         ? *(const float4*)&x[(size_t)row * N_NODES + gk]
                         : make_float4(0.f, 0.f, 0.f, 0.f);
            *(float4*)&sX[r * G1_KCP + c4 * 4] = v;
        }
        __syncthreads();

#pragma unroll 4
        for (int kk = 0; kk < G1_KC; kk += 4) {
            ulonglong2 xa = *(const ulonglong2*)&sX[tid * G1_KCP + kk];
            ulonglong2 xb = *(const ulonglong2*)&sX[(tid + 128) * G1_KCP + kk];
#pragma unroll
            for (int j = 0; j < F_HID; ++j) {
                ulonglong2 w = *(const ulonglong2*)&sW[j * G1_KC + kk];
                acc[0][j] = ffma2(xa.x, w.x, acc[0][j]);
                acc[0][j] = ffma2(xa.y, w.y, acc[0][j]);
                acc[1][j] = ffma2(xb.x, w.x, acc[1][j]);
                acc[1][j] = ffma2(xb.y, w.y, acc[1][j]);
            }
        }
    }

#pragma unroll
    for (int r = 0; r < 2; ++r) {
        int row = row0 + tid + r * 128;
        if (row < N_NODES) {
#pragma unroll
            for (int j = 0; j < F_HID; ++j) {
                float2 v = funpack(acc[r][j]);
                atomicAdd(&g_h1[row * F_HID + j], v.x + v.y);
            }
        }
    }
}

// ---------------- 16-wide propagation ----------------
__global__ void k_self1() {
    int t = blockIdx.x * blockDim.x + threadIdx.x;
    if (t >= N_NODES * 4) return;
    int i = t >> 2;
    float iv = g_inv[i], c = iv * iv;
    float4 v = *(const float4*)&g_h1[t * 4];
    v.x *= c; v.y *= c; v.z *= c; v.w *= c;
    *(float4*)&g_a1[t * 4] = v;
}

template <int L>
__global__ void k_edge_agg(const int* __restrict__ src, const int* __restrict__ dst) {
    int t = blockIdx.x * blockDim.x + threadIdx.x;
    if (t >= E_EDGES * 4) return;
    int e = t >> 2, q = t & 3;
    int s = __ldg(src + e), d = __ldg(dst + e);
    const float* feat  = (L == 1) ? g_h1 : g_hr;
    float*       accum = (L == 1) ? g_a1 : g_p2;
    float c = g_inv[s] * g_inv[d];
    float4 v = *(const float4*)&feat[s * F_HID + q * 4];
    float* a = &accum[d * F_HID + q * 4];
    atomicAdd(a + 0, v.x * c);
    atomicAdd(a + 1, v.y * c);
    atomicAdd(a + 2, v.z * c);
    atomicAdd(a + 3, v.w * c);
}

__global__ void k_relu_self2(const float* __restrict__ b1) {
    int t = blockIdx.x * blockDim.x + threadIdx.x;
    if (t >= N_NODES * 4) return;
    int i = t >> 2, q = t & 3;
    float iv = g_inv[i], c = iv * iv;
    float4 b = *(const float4*)&b1[q * 4];
    float4 h = *(const float4*)&g_a1[t * 4];
    h.x = fmaxf(h.x + b.x, 0.f); h.y = fmaxf(h.y + b.y, 0.f);
    h.z = fmaxf(h.z + b.z, 0.f); h.w = fmaxf(h.w + b.w, 0.f);
    *(float4*)&g_hr[t * 4] = h;
    float4 p = make_float4(h.x * c, h.y * c, h.z * c, h.w * c);
    *(float4*)&g_p2[t * 4] = p;
}

// ---------------- GEMM2 + bias + log_softmax, fused ----------------
// Block = 256 threads, 8 rows/block. Row-pairs packed into smem sPp (no giant
// register tile -> no spills). Inner loop: float4 W2 loads, f32x2 FFMA, float4
// smem stores. Then one warp per row does max / lse / write with float4.
__global__ void __launch_bounds__(256) k_gemm2(const float* __restrict__ W2,
                                               const float* __restrict__ b2,
                                               float* __restrict__ out) {
    extern __shared__ float sZ[];        // [8][N_NODES] = 160000 B
    __shared__ ull sPp[4 * F_HID];       // packed row pairs of p2
    const int tid  = threadIdx.x;
    const int row0 = blockIdx.x * 8;

    if (tid < 4 * F_HID) {
        int pr = tid >> 4, k = tid & 15;
        sPp[tid] = fpack(g_p2[(row0 + 2 * pr) * F_HID + k],
                         g_p2[(row0 + 2 * pr + 1) * F_HID + k]);
    }
    __syncthreads();

    for (int c4 = tid; c4 < N_NODES / 4; c4 += 256) {
        const int c = c4 * 4;
        float4 bv = *(const float4*)&b2[c];
        ull bd0 = fpack(bv.x, bv.x), bd1 = fpack(bv.y, bv.y);
        ull bd2 = fpack(bv.z, bv.z), bd3 = fpack(bv.w, bv.w);
        ull acc[4][4];
#pragma unroll
        for (int pr = 0; pr < 4; ++pr) {
            acc[pr][0] = bd0; acc[pr][1] = bd1; acc[pr][2] = bd2; acc[pr][3] = bd3;
        }
#pragma unroll
        for (int k = 0; k < F_HID; ++k) {
            float4 w = *(const float4*)&W2[k * N_NODES + c];
            ull w0 = fpack(w.x, w.x), w1 = fpack(w.y, w.y);
            ull w2 = fpack(w.z, w.z), w3 = fpack(w.w, w.w);
#pragma unroll
            for (int pr = 0; pr < 4; ++pr) {
                ull pp = sPp[pr * F_HID + k];   // broadcast LDS.64
                acc[pr][0] = ffma2(pp, w0, acc[pr][0]);
                acc[pr][1] = ffma2(pp, w1, acc[pr][1]);
                acc[pr][2] = ffma2(pp, w2, acc[pr][2]);
                acc[pr][3] = ffma2(pp, w3, acc[pr][3]);
            }
        }
#pragma unroll
        for (int pr = 0; pr < 4; ++pr) {
            float2 a0 = funpack(acc[pr][0]), a1 = funpack(acc[pr][1]);
            float2 a2 = funpack(acc[pr][2]), a3 = funpack(acc[pr][3]);
            *(float4*)&sZ[(2 * pr)     * N_NODES + c] = make_float4(a0.x, a1.x, a2.x, a3.x);
            *(float4*)&sZ[(2 * pr + 1) * N_NODES + c] = make_float4(a0.y, a1.y, a2.y, a3.y);
        }
    }
    __syncthreads();

    const int warp = tid >> 5, lane = tid & 31;
    const float4* z4 = (const float4*)(sZ + warp * N_NODES);

    float m = -INFINITY;
    for (int i = lane; i < N_NODES / 4; i += 32) {
        float4 v = z4[i];
        m = fmaxf(m, fmaxf(fmaxf(v.x, v.y), fmaxf(v.z, v.w)));
    }
#pragma unroll
    for (int o = 16; o; o >>= 1) m = fmaxf(m, __shfl_xor_sync(0xffffffffu, m, o));

    float s = 0.0f;
    for (int i = lane; i < N_NODES / 4; i += 32) {
        float4 v = z4[i];
        s += __expf(v.x - m) + __expf(v.y - m) + __expf(v.z - m) + __expf(v.w - m);
    }
#pragma unroll
    for (int o = 16; o; o >>= 1) s += __shfl_xor_sync(0xffffffffu, s, o);

    float lse = m + logf(s);
    float4* orow = (float4*)(out + (size_t)(row0 + warp) * N_NODES);
    for (int i = lane; i < N_NODES / 4; i += 32) {
        float4 v = z4[i];
        orow[i] = make_float4(v.x - lse, v.y - lse, v.z - lse, v.w - lse);
    }
}

// ---------------- launch ----------------
extern "C" void kernel_launch(void* const* d_in, const int* in_sizes, int n_in,
                              void* d_out, int out_size) {
    const float* x   = (const float*)d_in[0];
    const int*   src = (const int*)  d_in[1];
    const int*   dst = (const int*)  d_in[2];
    const float* W1  = (const float*)d_in[3];
    const float* b1  = (const float*)d_in[4];
    const float* W2  = (const float*)d_in[5];
    const float* b2  = (const float*)d_in[6];
    float* out = (float*)d_out;

    const int smem2 = 8 * N_NODES * (int)sizeof(float);  // 160 KB
    cudaFuncSetAttribute(k_gemm2, cudaFuncAttributeMaxDynamicSharedMemorySize, smem2);

    k_init     <<<(N_NODES * F_HID + 255) / 256, 256>>>();
    k_deg_edges<<<(E_EDGES + 255) / 256, 256>>>(dst);
    k_rsqrt    <<<(N_NODES + 255) / 256, 256>>>();

    dim3 g1((N_NODES + G1_ROWS - 1) / G1_ROWS, G1_KS);   // (20, 16)
    k_gemm1<<<g1, 128>>>(x, W1);

    k_self1<<<(N_NODES * 4 + 255) / 256, 256>>>();
    k_edge_agg<1><<<(E_EDGES * 4 + 255) / 256, 256>>>(src, dst);

    k_relu_self2<<<(N_NODES * 4 + 255) / 256, 256>>>(b1);
    k_edge_agg<2><<<(E_EDGES * 4 + 255) / 256, 256>>>(src, dst);

    k_gemm2<<<N_NODES / 8, 256, smem2>>>(W2, b2, out);
}